// round 7
// baseline (speedup 1.0000x reference)
#include <cuda_runtime.h>
#include <stdint.h>

// ZGate(D=2, s=1, index=2) on (2^24, 2) complex64 state, float32-coerced out:
//   out[k] = x_re[k] * (-1)^((k >> 22) & 1),  k in [0, 2^25).
// Contract (established R1-R4): inputs x_re, x_im float32[2^25];
// output buffer = 2^25 float32 = real part only.

#define N_COMPLEX  (1u << 25)
#define TPB        256u
#define VPT        4u                      // float4 groups per iteration/thread
#define CHUNK      (VPT * TPB)             // float4 groups per chunk (1024)
#define N_CHUNKS   ((N_COMPLEX >> 2) / CHUNK)   // 8192
#define GRID       (148u * 8u)             // persistent: one wave, 8 CTAs/SM

// Persistent grid-stride: each block walks chunks; per iteration 4 independent
// front-batched LDG.128 per thread (proven best MLP shape from R5).
__global__ void __launch_bounds__(256) zgate_real_persist(
    const uint4* __restrict__ xr,
    uint4* __restrict__ out)
{
    for (unsigned c = blockIdx.x; c < N_CHUNKS; c += gridDim.x) {
        unsigned base = c * CHUNK + threadIdx.x;

        uint4 v[VPT];
#pragma unroll
        for (int k = 0; k < (int)VPT; k++)
            v[k] = __ldcs(&xr[base + k * TPB]);

#pragma unroll
        for (int k = 0; k < (int)VPT; k++) {
            unsigned g = base + k * TPB;              // float4-group index
            // bit22 of float index (4g) == bit20 of g; flip fp32 sign via XOR
            unsigned m = ((g >> 20) & 1u) << 31;
            __stcs(&out[g],
                   make_uint4(v[k].x ^ m, v[k].y ^ m, v[k].z ^ m, v[k].w ^ m));
        }
    }
}

// Bounds-safe scalar fallback (any n / alignment).
__global__ void __launch_bounds__(256) zgate_real_scalar(
    const float* __restrict__ xr,
    float* __restrict__ out,
    unsigned n)
{
    unsigned k = blockIdx.x * blockDim.x + threadIdx.x;
    if (k >= n) return;
    float s = ((k >> 22) & 1u) ? -1.0f : 1.0f;
    out[k] = xr[k] * s;
}

// Fallback: full interleaved complex (if out buffer is 2^26 floats).
__global__ void __launch_bounds__(256) zgate_cplx_vec4(
    const float4* __restrict__ xr,
    const float4* __restrict__ xi,
    float4* __restrict__ out,
    unsigned n4)
{
    unsigned t = blockIdx.x * blockDim.x + threadIdx.x;
    if (t >= n4) return;
    float4 r  = xr[t];
    float4 im = xi[t];
    float s = ((t >> 20) & 1u) ? -1.0f : 1.0f;
    out[2u * t]      = make_float4(r.x * s, im.x * s, r.y * s, im.y * s);
    out[2u * t + 1u] = make_float4(r.z * s, im.z * s, r.w * s, im.w * s);
}

extern "C" void kernel_launch(void* const* d_in, const int* in_sizes, int n_in,
                              void* d_out, int out_size)
{
    const float* xr = (const float*)d_in[0];
    const float* xi = (n_in >= 2) ? (const float*)d_in[1] : xr;

    uintptr_t a = (uintptr_t)xr | (uintptr_t)d_out;
    bool aligned16 = (a & 0xF) == 0;

    if ((unsigned)out_size >= (N_COMPLEX << 1)) {
        unsigned n4 = N_COMPLEX >> 2;
        zgate_cplx_vec4<<<n4 / TPB, TPB>>>(
            (const float4*)xr, (const float4*)xi, (float4*)d_out, n4);
        return;
    }

    unsigned n = (unsigned)out_size;
    if (n_in >= 1 && in_sizes && in_sizes[0] > 0 &&
        n > (unsigned)in_sizes[0])
        n = (unsigned)in_sizes[0];

    if (aligned16 && n == N_COMPLEX) {
        zgate_real_persist<<<GRID, TPB>>>((const uint4*)xr, (uint4*)d_out);
    } else {
        unsigned blocks = (n + TPB - 1) / TPB;
        zgate_real_scalar<<<blocks, TPB>>>(xr, (float*)d_out, n);
    }
}

// round 8
// speedup vs baseline: 1.0471x; 1.0471x over previous
#include <cuda_runtime.h>
#include <stdint.h>

// ZGate(D=2, s=1, index=2) on (2^24, 2) complex64 state, float32-coerced out:
//   out[k] = x_re[k] * (-1)^((k >> 22) & 1),  k in [0, 2^25).
// Contract (established R1-R4): inputs x_re, x_im float32[2^25];
// output buffer = 2^25 float32 = real part only.
//
// R5 shape (flat, VPT=4, front-batched LDG.128, 26 regs) is the proven best;
// this round tests TPB=512 (same per-warp MLP, half the CTAs).

#define N_COMPLEX (1u << 25)
#define TPB       512u
#define VPT       4u

__global__ void __launch_bounds__(512) zgate_real_vec4x4(
    const uint4* __restrict__ xr,
    uint4* __restrict__ out)
{
    unsigned base = blockIdx.x * (VPT * TPB) + threadIdx.x;

    uint4 v[VPT];
#pragma unroll
    for (int k = 0; k < (int)VPT; k++)
        v[k] = __ldcs(&xr[base + k * TPB]);

#pragma unroll
    for (int k = 0; k < (int)VPT; k++) {
        unsigned g = base + k * TPB;               // float4-group index
        // bit22 of float index (4g) == bit20 of g; flip fp32 sign via XOR
        unsigned m = ((g >> 20) & 1u) << 31;
        __stcs(&out[g],
               make_uint4(v[k].x ^ m, v[k].y ^ m, v[k].z ^ m, v[k].w ^ m));
    }
}

// Bounds-safe scalar fallback (any n / alignment).
__global__ void __launch_bounds__(256) zgate_real_scalar(
    const float* __restrict__ xr,
    float* __restrict__ out,
    unsigned n)
{
    unsigned k = blockIdx.x * blockDim.x + threadIdx.x;
    if (k >= n) return;
    float s = ((k >> 22) & 1u) ? -1.0f : 1.0f;
    out[k] = xr[k] * s;
}

// Fallback: full interleaved complex (if out buffer is 2^26 floats).
__global__ void __launch_bounds__(256) zgate_cplx_vec4(
    const float4* __restrict__ xr,
    const float4* __restrict__ xi,
    float4* __restrict__ out,
    unsigned n4)
{
    unsigned t = blockIdx.x * blockDim.x + threadIdx.x;
    if (t >= n4) return;
    float4 r  = xr[t];
    float4 im = xi[t];
    float s = ((t >> 20) & 1u) ? -1.0f : 1.0f;
    out[2u * t]      = make_float4(r.x * s, im.x * s, r.y * s, im.y * s);
    out[2u * t + 1u] = make_float4(r.z * s, im.z * s, r.w * s, im.w * s);
}

extern "C" void kernel_launch(void* const* d_in, const int* in_sizes, int n_in,
                              void* d_out, int out_size)
{
    const float* xr = (const float*)d_in[0];
    const float* xi = (n_in >= 2) ? (const float*)d_in[1] : xr;

    uintptr_t a = (uintptr_t)xr | (uintptr_t)d_out;
    bool aligned16 = (a & 0xF) == 0;

    if ((unsigned)out_size >= (N_COMPLEX << 1)) {
        unsigned n4 = N_COMPLEX >> 2;
        zgate_cplx_vec4<<<n4 / 256u, 256u>>>(
            (const float4*)xr, (const float4*)xi, (float4*)d_out, n4);
        return;
    }

    unsigned n = (unsigned)out_size;
    if (n_in >= 1 && in_sizes && in_sizes[0] > 0 &&
        n > (unsigned)in_sizes[0])
        n = (unsigned)in_sizes[0];

    if (aligned16 && n == N_COMPLEX) {
        unsigned n4 = n >> 2;                      // 2^23 float4 groups
        unsigned blocks = n4 / (VPT * TPB);        // 4096
        zgate_real_vec4x4<<<blocks, TPB>>>((const uint4*)xr, (uint4*)d_out);
    } else {
        unsigned blocks = (n + 255u) / 256u;
        zgate_real_scalar<<<blocks, 256u>>>(xr, (float*)d_out, n);
    }
}